// round 13
// baseline (speedup 1.0000x reference)
#include <cuda_runtime.h>
#include <cstdint>

#define GRID      592        // 4 blocks/SM on 148 SMs
#define NTHREADS  256
#define STAGES    2
#define TILE      1024       // elements per tile
// per-stage byte layout: inp 8192 | w 4096 | ref 4096 | mask 4096
#define INP_B     8192
#define WRM_B     4096
#define STAGE_B   (INP_B + 3 * WRM_B)    // 20480
#define SMEM_TOTAL (STAGES * STAGE_B)    // 40960 (dynamic)
#define TX_BYTES  STAGE_B

__device__ float        g_psm[GRID];
__device__ float        g_psf[GRID];
__device__ int          g_pcnt[GRID];
__device__ unsigned int g_count = 0;
__device__ unsigned int g_tile  = 0;   // dynamic tile dispenser (reset each launch)

__device__ __forceinline__ uint32_t smem_u32(const void* p) {
    return (uint32_t)__cvta_generic_to_shared(p);
}
__device__ __forceinline__ void mbar_init(uint32_t a, uint32_t cnt) {
    asm volatile("mbarrier.init.shared.b64 [%0], %1;" :: "r"(a), "r"(cnt) : "memory");
}
__device__ __forceinline__ void mbar_expect_tx(uint32_t a, uint32_t bytes) {
    asm volatile("mbarrier.arrive.expect_tx.shared.b64 _, [%0], %1;"
                 :: "r"(a), "r"(bytes) : "memory");
}
__device__ __forceinline__ void mbar_wait(uint32_t a, uint32_t parity) {
    uint32_t done;
    asm volatile(
        "{\n\t.reg .pred p;\n\t"
        "mbarrier.try_wait.parity.acquire.cta.shared::cta.b64 p, [%1], %2;\n\t"
        "selp.b32 %0, 1, 0, p;\n\t}"
        : "=r"(done) : "r"(a), "r"(parity) : "memory");
    if (!done) {
        asm volatile(
            "{\n\t.reg .pred P1;\n\t"
            "WL_%=:\n\t"
            "mbarrier.try_wait.parity.acquire.cta.shared::cta.b64 P1, [%0], %1, 0x989680;\n\t"
            "@P1 bra.uni WD_%=;\n\t"
            "bra.uni WL_%=;\n\t"
            "WD_%=:\n\t}"
            :: "r"(a), "r"(parity) : "memory");
    }
}
__device__ __forceinline__ void bulk_g2s(uint32_t dst, const void* src,
                                         uint32_t bytes, uint32_t mbar) {
    asm volatile(
        "cp.async.bulk.shared::cluster.global.mbarrier::complete_tx::bytes "
        "[%0], [%1], %2, [%3];"
        :: "r"(dst), "l"(src), "r"(bytes), "r"(mbar) : "memory");
}

__global__ __launch_bounds__(NTHREADS) void topo_loss_kernel(
    const char* __restrict__ inp,   // N * 8 bytes  (N elements x 2 channels f32)
    const char* __restrict__ w,     // N * 4 bytes
    const char* __restrict__ ref,   // N * 4 bytes
    const char* __restrict__ mask,  // N * 4 bytes (int32 bool)
    int ntiles,                     // N / TILE
    int n_total,
    float* __restrict__ out)
{
    extern __shared__ __align__(128) char dsmem[];
    __shared__ __align__(8) unsigned long long mbar_store[STAGES];
    __shared__ int s_t[STAGES];   // tile index held by each stage; -1 = exhausted

    const int bid = blockIdx.x;
    const int tid = threadIdx.x;

    uint32_t mbar[STAGES];
    #pragma unroll
    for (int s = 0; s < STAGES; s++) mbar[s] = smem_u32(&mbar_store[s]);

    if (tid == 0) {
        #pragma unroll
        for (int s = 0; s < STAGES; s++) mbar_init(mbar[s], 1);
    }
    __syncthreads();

    // fetch-and-fill helper semantics (tid0 only):
    //  grab a tile from the global dispenser; if exhausted, publish -1 and
    //  flip the barrier with a zero-byte expect_tx (arrive completes phase).
    auto fill_stage = [&](int s) {
        unsigned int t = atomicAdd(&g_tile, 1u);
        if (t < (unsigned int)ntiles) {
            s_t[s] = (int)t;
            uint32_t d = smem_u32(dsmem + s * STAGE_B);
            const long long tt = (long long)t;
            mbar_expect_tx(mbar[s], TX_BYTES);
            bulk_g2s(d,                   inp  + tt * (long long)INP_B, INP_B, mbar[s]);
            bulk_g2s(d + INP_B,           w    + tt * (long long)WRM_B, WRM_B, mbar[s]);
            bulk_g2s(d + INP_B + WRM_B,   ref  + tt * (long long)WRM_B, WRM_B, mbar[s]);
            bulk_g2s(d + INP_B + 2*WRM_B, mask + tt * (long long)WRM_B, WRM_B, mbar[s]);
        } else {
            s_t[s] = -1;
            mbar_expect_tx(mbar[s], 0);   // completes the phase immediately
        }
    };

    // ---- prologue: fill both stages from the dispenser ----
    if (tid == 0) {
        #pragma unroll
        for (int s = 0; s < STAGES; s++) fill_stage(s);
    }
    // no __syncthreads needed: consumers synchronize via mbar_wait (acquire)

    float sm = 0.0f;
    float sf = 0.0f;
    int   cnt = 0;

    for (int k = 0; ; k++) {
        const int s = k & (STAGES - 1);
        const uint32_t parity = (k >> 1) & 1;   // STAGES == 2
        mbar_wait(mbar[s], parity);

        const int t = s_t[s];     // published before arrive (release->acquire)
        if (t < 0) break;         // dispenser exhausted; later stages also -1

        const char* base = dsmem + s * STAGE_B;
        const float4* s_inp = (const float4*)(base);                    // 512 f4
        const float4* s_w   = (const float4*)(base + INP_B);            // 256 f4
        const float4* s_ref = (const float4*)(base + INP_B + WRM_B);    // 256 f4
        const int4*   s_m   = (const int4*)  (base + INP_B + 2*WRM_B);  // 256 i4

        // TILE=1024 elems / 256 threads -> 4 elems/thread
        float4 a  = s_inp[2 * tid];       // elems 4j, 4j+1 : (c0,c1,c0,c1)
        float4 b  = s_inp[2 * tid + 1];   // elems 4j+2, 4j+3
        float4 wv = s_w[tid];
        float4 rv = s_ref[tid];
        int4   mv = s_m[tid];

        float e0 = a.y * wv.x - rv.x;
        float e1 = a.w * wv.y - rv.y;
        float e2 = b.y * wv.z - rv.z;
        float e3 = b.w * wv.w - rv.w;

        float s0 = e0 * e0, s1 = e1 * e1, s2 = e2 * e2, s3 = e3 * e3;

        sf += s0 + s1 + s2 + s3;
        sm += (mv.x ? s0 : 0.0f) + (mv.y ? s1 : 0.0f)
            + (mv.z ? s2 : 0.0f) + (mv.w ? s3 : 0.0f);
        cnt += (mv.x ? 1 : 0) + (mv.y ? 1 : 0) + (mv.z ? 1 : 0) + (mv.w ? 1 : 0);

        __syncthreads();   // whole block done reading stage s

        if (tid == 0) fill_stage(s);
    }

    // ---- residual elements (n_total not divisible by TILE) ----
    {
        const int base_i = ntiles * TILE;
        const float* inpf  = (const float*)inp;
        const float* wf    = (const float*)w;
        const float* reff  = (const float*)ref;
        const int*   maskf = (const int*)mask;
        for (int i = base_i + bid * NTHREADS + tid; i < n_total; i += GRID * NTHREADS) {
            float lik = inpf[2 * i + 1];
            float e = lik * wf[i] - reff[i];
            float sq = e * e;
            sf += sq;
            if (maskf[i]) { sm += sq; cnt += 1; }
        }
    }

    // ---- warp reduction ----
    #pragma unroll
    for (int off = 16; off > 0; off >>= 1) {
        sm  += __shfl_down_sync(0xFFFFFFFFu, sm, off);
        sf  += __shfl_down_sync(0xFFFFFFFFu, sf, off);
        cnt += __shfl_down_sync(0xFFFFFFFFu, cnt, off);
    }

    __shared__ float s_psm[8];
    __shared__ float s_psf[8];
    __shared__ int   s_pcnt[8];
    __shared__ int   s_is_last;

    const int lane = tid & 31;
    const int wid  = tid >> 5;
    if (lane == 0) { s_psm[wid] = sm; s_psf[wid] = sf; s_pcnt[wid] = cnt; }
    __syncthreads();

    if (tid == 0) {
        float bsm = 0.0f, bsf = 0.0f;
        int bcnt = 0;
        #pragma unroll
        for (int q = 0; q < NTHREADS / 32; q++) {
            bsm += s_psm[q]; bsf += s_psf[q]; bcnt += s_pcnt[q];
        }
        g_psm[bid]  = bsm;
        g_psf[bid]  = bsf;
        g_pcnt[bid] = bcnt;
        __threadfence();
        unsigned int prev = atomicAdd(&g_count, 1u);
        s_is_last = (prev == gridDim.x - 1);
    }
    __syncthreads();

    if (s_is_last) {
        double dsm = 0.0, dsf = 0.0, dcnt = 0.0;
        for (int q = tid; q < GRID; q += NTHREADS) {
            dsm  += (double)g_psm[q];
            dsf  += (double)g_psf[q];
            dcnt += (double)g_pcnt[q];
        }
        #pragma unroll
        for (int off = 16; off > 0; off >>= 1) {
            dsm  += __shfl_down_sync(0xFFFFFFFFu, dsm, off);
            dsf  += __shfl_down_sync(0xFFFFFFFFu, dsf, off);
            dcnt += __shfl_down_sync(0xFFFFFFFFu, dcnt, off);
        }
        __shared__ double f_sm[8];
        __shared__ double f_sf[8];
        __shared__ double f_cnt[8];
        if (lane == 0) { f_sm[wid] = dsm; f_sf[wid] = dsf; f_cnt[wid] = dcnt; }
        __syncthreads();
        if (tid == 0) {
            double tsm = 0.0, tsf = 0.0, tcnt = 0.0;
            #pragma unroll
            for (int q = 0; q < NTHREADS / 32; q++) {
                tsm += f_sm[q]; tsf += f_sf[q]; tcnt += f_cnt[q];
            }
            double masked_mean = tsm / (tcnt > 1.0 ? tcnt : 1.0);
            double full_mean   = tsf / (double)n_total;
            out[0] = (float)((tcnt > 0.0) ? masked_mean : full_mean);
            g_count = 0;   // reset for next graph replay
            g_tile  = 0;   // reset the tile dispenser for next replay
        }
    }
}

extern "C" void kernel_launch(void* const* d_in, const int* in_sizes, int n_in,
                              void* d_out, int out_size) {
    // 0: inputs (N*2 f32), 1: weight (N f32), 2: ref (N f32), 3: mask (N int32)
    const char* inp  = (const char*)d_in[0];
    const char* w    = (const char*)d_in[1];
    const char* ref  = (const char*)d_in[2];
    const char* mask = (const char*)d_in[3];
    float* out = (float*)d_out;

    const int n      = in_sizes[1];   // total elements (B*H*W)
    const int ntiles = n / TILE;

    static int smem_set = 0;
    if (!smem_set) {
        cudaFuncSetAttribute(topo_loss_kernel,
                             cudaFuncAttributeMaxDynamicSharedMemorySize, SMEM_TOTAL);
        smem_set = 1;
    }

    topo_loss_kernel<<<GRID, NTHREADS, SMEM_TOTAL>>>(inp, w, ref, mask, ntiles, n, out);
}

// round 14
// speedup vs baseline: 1.0987x; 1.0987x over previous
#include <cuda_runtime.h>
#include <cstdint>

#define GRID      592        // 4 blocks/SM on 148 SMs
#define NTHREADS  256
#define STAGES    2
#define TILE      1024       // elements per tile
// per-stage byte layout: inp 8192 | w 4096 | ref 4096 | mask 4096
#define INP_B     8192
#define WRM_B     4096
#define STAGE_B   (INP_B + 3 * WRM_B)    // 20480
#define SMEM_TOTAL (STAGES * STAGE_B)    // 40960 (dynamic)
#define TX_BYTES  STAGE_B

__device__ float        g_psm[GRID];
__device__ float        g_psf[GRID];
__device__ int          g_pcnt[GRID];
__device__ unsigned int g_count = 0;

__device__ __forceinline__ uint32_t smem_u32(const void* p) {
    return (uint32_t)__cvta_generic_to_shared(p);
}
__device__ __forceinline__ void mbar_init(uint32_t a, uint32_t cnt) {
    asm volatile("mbarrier.init.shared.b64 [%0], %1;" :: "r"(a), "r"(cnt) : "memory");
}
__device__ __forceinline__ void mbar_expect_tx(uint32_t a, uint32_t bytes) {
    asm volatile("mbarrier.arrive.expect_tx.shared.b64 _, [%0], %1;"
                 :: "r"(a), "r"(bytes) : "memory");
}
__device__ __forceinline__ void mbar_wait(uint32_t a, uint32_t parity) {
    uint32_t done;
    asm volatile(
        "{\n\t.reg .pred p;\n\t"
        "mbarrier.try_wait.parity.acquire.cta.shared::cta.b64 p, [%1], %2;\n\t"
        "selp.b32 %0, 1, 0, p;\n\t}"
        : "=r"(done) : "r"(a), "r"(parity) : "memory");
    if (!done) {
        asm volatile(
            "{\n\t.reg .pred P1;\n\t"
            "WL_%=:\n\t"
            "mbarrier.try_wait.parity.acquire.cta.shared::cta.b64 P1, [%0], %1, 0x989680;\n\t"
            "@P1 bra.uni WD_%=;\n\t"
            "bra.uni WL_%=;\n\t"
            "WD_%=:\n\t}"
            :: "r"(a), "r"(parity) : "memory");
    }
}
__device__ __forceinline__ void bulk_g2s(uint32_t dst, const void* src,
                                         uint32_t bytes, uint32_t mbar) {
    asm volatile(
        "cp.async.bulk.shared::cluster.global.mbarrier::complete_tx::bytes "
        "[%0], [%1], %2, [%3];"
        :: "r"(dst), "l"(src), "r"(bytes), "r"(mbar) : "memory");
}

__global__ __launch_bounds__(NTHREADS) void topo_loss_kernel(
    const char* __restrict__ inp,   // N * 8 bytes  (N elements x 2 channels f32)
    const char* __restrict__ w,     // N * 4 bytes
    const char* __restrict__ ref,   // N * 4 bytes
    const char* __restrict__ mask,  // N * 4 bytes (int32 bool)
    int ntiles,                     // N / TILE
    int n_total,
    float* __restrict__ out)
{
    extern __shared__ __align__(128) char dsmem[];
    __shared__ __align__(8) unsigned long long mbar_store[STAGES];

    const int bid = blockIdx.x;
    const int tid = threadIdx.x;

    uint32_t mbar[STAGES];
    #pragma unroll
    for (int s = 0; s < STAGES; s++) mbar[s] = smem_u32(&mbar_store[s]);

    if (tid == 0) {
        #pragma unroll
        for (int s = 0; s < STAGES; s++) mbar_init(mbar[s], 1);
    }
    __syncthreads();

    const int kmax = (bid < ntiles) ? (ntiles - bid + GRID - 1) / GRID : 0;

    // ---- prologue: fill the pipeline ----
    if (tid == 0) {
        #pragma unroll
        for (int k = 0; k < STAGES; k++) {
            if (k < kmax) {
                const long long t = bid + (long long)k * GRID;
                uint32_t d = smem_u32(dsmem + k * STAGE_B);
                mbar_expect_tx(mbar[k], TX_BYTES);
                bulk_g2s(d,                   inp  + t * (long long)INP_B, INP_B, mbar[k]);
                bulk_g2s(d + INP_B,           w    + t * (long long)WRM_B, WRM_B, mbar[k]);
                bulk_g2s(d + INP_B + WRM_B,   ref  + t * (long long)WRM_B, WRM_B, mbar[k]);
                bulk_g2s(d + INP_B + 2*WRM_B, mask + t * (long long)WRM_B, WRM_B, mbar[k]);
            }
        }
    }

    float sm = 0.0f;
    float sf = 0.0f;
    int   cnt = 0;

    for (int k = 0; k < kmax; k++) {
        const int s = k & (STAGES - 1);
        const uint32_t parity = (k >> 1) & 1;   // STAGES == 2
        mbar_wait(mbar[s], parity);

        const char* base = dsmem + s * STAGE_B;
        const float4* s_inp = (const float4*)(base);                    // 512 f4
        const float4* s_w   = (const float4*)(base + INP_B);            // 256 f4
        const float4* s_ref = (const float4*)(base + INP_B + WRM_B);    // 256 f4
        const int4*   s_m   = (const int4*)  (base + INP_B + 2*WRM_B);  // 256 i4

        // TILE=1024 elems / 256 threads -> 4 elems/thread
        float4 a  = s_inp[2 * tid];       // elems 4j, 4j+1 : (c0,c1,c0,c1)
        float4 b  = s_inp[2 * tid + 1];   // elems 4j+2, 4j+3
        float4 wv = s_w[tid];
        float4 rv = s_ref[tid];
        int4   mv = s_m[tid];

        float e0 = a.y * wv.x - rv.x;
        float e1 = a.w * wv.y - rv.y;
        float e2 = b.y * wv.z - rv.z;
        float e3 = b.w * wv.w - rv.w;

        float s0 = e0 * e0, s1 = e1 * e1, s2 = e2 * e2, s3 = e3 * e3;

        sf += s0 + s1 + s2 + s3;
        sm += (mv.x ? s0 : 0.0f) + (mv.y ? s1 : 0.0f)
            + (mv.z ? s2 : 0.0f) + (mv.w ? s3 : 0.0f);
        cnt += (mv.x ? 1 : 0) + (mv.y ? 1 : 0) + (mv.z ? 1 : 0) + (mv.w ? 1 : 0);

        __syncthreads();   // whole block done reading stage s

        // refill this slot for tile k + STAGES
        if (tid == 0 && (k + STAGES) < kmax) {
            const long long t = bid + (long long)(k + STAGES) * GRID;
            uint32_t d = smem_u32(dsmem + s * STAGE_B);
            mbar_expect_tx(mbar[s], TX_BYTES);
            bulk_g2s(d,                   inp  + t * (long long)INP_B, INP_B, mbar[s]);
            bulk_g2s(d + INP_B,           w    + t * (long long)WRM_B, WRM_B, mbar[s]);
            bulk_g2s(d + INP_B + WRM_B,   ref  + t * (long long)WRM_B, WRM_B, mbar[s]);
            bulk_g2s(d + INP_B + 2*WRM_B, mask + t * (long long)WRM_B, WRM_B, mbar[s]);
        }
    }

    // ---- residual elements (n_total not divisible by TILE) ----
    {
        const int base_i = ntiles * TILE;
        const float* inpf  = (const float*)inp;
        const float* wf    = (const float*)w;
        const float* reff  = (const float*)ref;
        const int*   maskf = (const int*)mask;
        for (int i = base_i + bid * NTHREADS + tid; i < n_total; i += GRID * NTHREADS) {
            float lik = inpf[2 * i + 1];
            float e = lik * wf[i] - reff[i];
            float sq = e * e;
            sf += sq;
            if (maskf[i]) { sm += sq; cnt += 1; }
        }
    }

    // ---- warp reduction ----
    #pragma unroll
    for (int off = 16; off > 0; off >>= 1) {
        sm  += __shfl_down_sync(0xFFFFFFFFu, sm, off);
        sf  += __shfl_down_sync(0xFFFFFFFFu, sf, off);
        cnt += __shfl_down_sync(0xFFFFFFFFu, cnt, off);
    }

    __shared__ float s_psm[8];
    __shared__ float s_psf[8];
    __shared__ int   s_pcnt[8];
    __shared__ int   s_is_last;

    const int lane = tid & 31;
    const int wid  = tid >> 5;
    if (lane == 0) { s_psm[wid] = sm; s_psf[wid] = sf; s_pcnt[wid] = cnt; }
    __syncthreads();

    if (tid == 0) {
        float bsm = 0.0f, bsf = 0.0f;
        int bcnt = 0;
        #pragma unroll
        for (int q = 0; q < NTHREADS / 32; q++) {
            bsm += s_psm[q]; bsf += s_psf[q]; bcnt += s_pcnt[q];
        }
        g_psm[bid]  = bsm;
        g_psf[bid]  = bsf;
        g_pcnt[bid] = bcnt;
        __threadfence();
        unsigned int prev = atomicAdd(&g_count, 1u);
        s_is_last = (prev == gridDim.x - 1);
    }
    __syncthreads();

    if (s_is_last) {
        double dsm = 0.0, dsf = 0.0, dcnt = 0.0;
        for (int q = tid; q < GRID; q += NTHREADS) {
            dsm  += (double)g_psm[q];
            dsf  += (double)g_psf[q];
            dcnt += (double)g_pcnt[q];
        }
        #pragma unroll
        for (int off = 16; off > 0; off >>= 1) {
            dsm  += __shfl_down_sync(0xFFFFFFFFu, dsm, off);
            dsf  += __shfl_down_sync(0xFFFFFFFFu, dsf, off);
            dcnt += __shfl_down_sync(0xFFFFFFFFu, dcnt, off);
        }
        __shared__ double f_sm[8];
        __shared__ double f_sf[8];
        __shared__ double f_cnt[8];
        if (lane == 0) { f_sm[wid] = dsm; f_sf[wid] = dsf; f_cnt[wid] = dcnt; }
        __syncthreads();
        if (tid == 0) {
            double tsm = 0.0, tsf = 0.0, tcnt = 0.0;
            #pragma unroll
            for (int q = 0; q < NTHREADS / 32; q++) {
                tsm += f_sm[q]; tsf += f_sf[q]; tcnt += f_cnt[q];
            }
            double masked_mean = tsm / (tcnt > 1.0 ? tcnt : 1.0);
            double full_mean   = tsf / (double)n_total;
            out[0] = (float)((tcnt > 0.0) ? masked_mean : full_mean);
            g_count = 0;   // reset for next graph replay
        }
    }
}

extern "C" void kernel_launch(void* const* d_in, const int* in_sizes, int n_in,
                              void* d_out, int out_size) {
    // 0: inputs (N*2 f32), 1: weight (N f32), 2: ref (N f32), 3: mask (N int32)
    const char* inp  = (const char*)d_in[0];
    const char* w    = (const char*)d_in[1];
    const char* ref  = (const char*)d_in[2];
    const char* mask = (const char*)d_in[3];
    float* out = (float*)d_out;

    const int n      = in_sizes[1];   // total elements (B*H*W)
    const int ntiles = n / TILE;

    static int smem_set = 0;
    if (!smem_set) {
        cudaFuncSetAttribute(topo_loss_kernel,
                             cudaFuncAttributeMaxDynamicSharedMemorySize, SMEM_TOTAL);
        smem_set = 1;
    }

    topo_loss_kernel<<<GRID, NTHREADS, SMEM_TOTAL>>>(inp, w, ref, mask, ntiles, n, out);
}